// round 14
// baseline (speedup 1.0000x reference)
#include <cuda_runtime.h>
#include <cuda_bf16.h>
#include <cstdint>

#define BB   64
#define NE   500
#define NR   500
#define NPAD 512
#define C1   151      // classes + 1
#define NC   150      // kept classes
#define KP   160      // padded K for dot products
#define TS   64       // tile size (rows/cols per block)
#define LDH  168      // smem row stride in bf16 halves
#define LDSB (LDH*2)  // smem row stride bytes = 336

// ---------------- scratch (device globals: no allocation allowed) ----------
__device__ __align__(16) __nv_bfloat16 g_ent_prob[(size_t)BB * NPAD * KP];
__device__ __align__(16) __nv_bfloat16 g_rs_prob [(size_t)BB * NPAD * KP];
__device__ __align__(16) __nv_bfloat16 g_ro_prob [(size_t)BB * NPAD * KP];
__device__ float g_ent_meta[(size_t)BB * NPAD * 8];   // x0,y0,x1,y1,cx,cy,score,norm2
__device__ float g_rel_meta[(size_t)BB * NPAD * 16];  // rs box(4), ro box(4), vec(4), n_rs, n_ro, pad2

// ---------------- fast softmax (one warp, one row) ---------------------------
// writes bf16 probs (first NC kept, KP-NC zero-padded); returns ||p||^2 in all
// lanes and max-prob-over-NC ("score") in all lanes.
__device__ __forceinline__ float softmax_row_fast(const float* __restrict__ lg,
                                                  __nv_bfloat16* __restrict__ prob,
                                                  int lane, float& score) {
    float v[5];
    float m = -1e30f, m150 = -1e30f;
#pragma unroll
    for (int k = 0; k < 5; k++) {
        int i = lane + k * 32;
        float x = (i < C1) ? lg[i] : -1e30f;
        v[k] = x;
        m = fmaxf(m, x);
        if (i < NC) m150 = fmaxf(m150, x);
    }
#pragma unroll
    for (int o = 16; o > 0; o >>= 1) {
        m    = fmaxf(m,    __shfl_xor_sync(0xffffffffu, m,    o));
        m150 = fmaxf(m150, __shfl_xor_sync(0xffffffffu, m150, o));
    }
    float s = 0.f;
#pragma unroll
    for (int k = 0; k < 5; k++) {
        int i = lane + k * 32;
        float ex = (i < C1) ? __expf(v[k] - m) : 0.f;
        v[k] = ex;
        s += ex;
    }
#pragma unroll
    for (int o = 16; o > 0; o >>= 1) s += __shfl_xor_sync(0xffffffffu, s, o);
    float inv = 1.f / s;
    float n2 = 0.f;
#pragma unroll
    for (int k = 0; k < 5; k++) {
        int i = lane + k * 32;
        if (i < KP) {
            float p = (i < NC) ? v[k] * inv : 0.f;
            prob[i] = __float2bfloat16(p);
            n2 += p * p;
        }
    }
#pragma unroll
    for (int o = 16; o > 0; o >>= 1) n2 += __shfl_xor_sync(0xffffffffu, n2, o);
    score = __expf(m150 - m) * inv;
    return n2;
}

// ---------------- stage 1: unified preprocessing (1 softmax per warp) -------
// task 0: entity rows  (b, e)   -> g_ent_prob + g_ent_meta
// task 1: rel-sub rows (b, r)   -> g_rs_prob  + rel_meta[0..3],[8..12],[14]
// task 2: rel-obj rows (b, r)   -> g_ro_prob  + rel_meta[4..7],[13],[15]
__global__ void pre_all(const float* __restrict__ boxes,
                        const float* __restrict__ logits,
                        const float* __restrict__ ro_logits,
                        const float* __restrict__ rs_logits,
                        const float* __restrict__ ro_box,
                        const float* __restrict__ rs_box,
                        const float* __restrict__ rel_vec,
                        const float* __restrict__ tsz) {
    int gw   = blockIdx.x * (blockDim.x >> 5) + (threadIdx.x >> 5);
    int lane = threadIdx.x & 31;
    int task = gw >> 15;              // / (BB*NPAD)
    int idx  = gw & (BB * NPAD - 1);
    int b    = idx >> 9;
    int row  = idx & (NPAD - 1);
    size_t rowi = (size_t)idx;

    if (task == 0) {
        __nv_bfloat16* prob = g_ent_prob + rowi * KP;
        float* meta = g_ent_meta + rowi * 8;
        if (row >= NE) {
            __nv_bfloat16 z = __float2bfloat16(0.f);
            for (int i = lane; i < KP; i += 32) prob[i] = z;
            if (lane < 8) meta[lane] = 0.f;
            return;
        }
        float score;
        float n2 = softmax_row_fast(logits + (size_t)(b * NE + row) * C1, prob, lane, score);
        if (lane == 0) {
            float H = tsz[b * 2 + 0], W = tsz[b * 2 + 1];
            const float* bx = boxes + ((size_t)(b * NE + row)) * 4;
            float cx = bx[0], cy = bx[1], w = bx[2], h = bx[3];
            meta[0] = (cx - 0.5f * w) * W;
            meta[1] = (cy - 0.5f * h) * H;
            meta[2] = (cx + 0.5f * w) * W;
            meta[3] = (cy + 0.5f * h) * H;
            meta[4] = cx * W;
            meta[5] = cy * H;
            meta[6] = score;
            meta[7] = n2;
        }
    } else if (task == 1) {
        __nv_bfloat16* prob = g_rs_prob + rowi * KP;
        float* meta = g_rel_meta + rowi * 16;
        if (row >= NR) {
            __nv_bfloat16 z = __float2bfloat16(0.f);
            for (int i = lane; i < KP; i += 32) prob[i] = z;
            if (lane == 0) {
                meta[0] = meta[1] = meta[2] = meta[3] = 0.f;
                meta[8] = meta[9] = meta[10] = meta[11] = 0.f;
                meta[12] = 0.f; meta[14] = 0.f;
            }
            return;
        }
        float score;
        float n2 = softmax_row_fast(rs_logits + (size_t)(b * NR + row) * C1, prob, lane, score);
        if (lane == 0) {
            float H = tsz[b * 2 + 0], W = tsz[b * 2 + 1];
            size_t bi = (size_t)(b * NR + row) * 4;
            const float* sb = rs_box + bi;
            const float* rv = rel_vec + bi;
            float cx = sb[0], cy = sb[1], w = sb[2], h = sb[3];
            meta[0] = (cx - 0.5f * w) * W; meta[1] = (cy - 0.5f * h) * H;
            meta[2] = (cx + 0.5f * w) * W; meta[3] = (cy + 0.5f * h) * H;
            meta[8]  = rv[0] * W; meta[9]  = rv[1] * H;
            meta[10] = rv[2] * W; meta[11] = rv[3] * H;
            meta[12] = n2;
            meta[14] = 0.f;
        }
    } else {
        __nv_bfloat16* prob = g_ro_prob + rowi * KP;
        float* meta = g_rel_meta + rowi * 16;
        if (row >= NR) {
            __nv_bfloat16 z = __float2bfloat16(0.f);
            for (int i = lane; i < KP; i += 32) prob[i] = z;
            if (lane == 0) {
                meta[4] = meta[5] = meta[6] = meta[7] = 0.f;
                meta[13] = 0.f; meta[15] = 0.f;
            }
            return;
        }
        float score;
        float n2 = softmax_row_fast(ro_logits + (size_t)(b * NR + row) * C1, prob, lane, score);
        if (lane == 0) {
            float H = tsz[b * 2 + 0], W = tsz[b * 2 + 1];
            size_t bi = (size_t)(b * NR + row) * 4;
            const float* ob = ro_box + bi;
            float cx = ob[0], cy = ob[1], w = ob[2], h = ob[3];
            meta[4] = (cx - 0.5f * w) * W; meta[5] = (cy - 0.5f * h) * H;
            meta[6] = (cx + 0.5f * w) * W; meta[7] = (cy + 0.5f * h) * H;
            meta[13] = n2;
            meta[15] = 0.f;
        }
    }
}

// ---------------- mma / ldmatrix helpers ------------------------------------
__device__ __forceinline__ void ldsm4(unsigned& r0, unsigned& r1, unsigned& r2,
                                      unsigned& r3, unsigned addr) {
    asm volatile("ldmatrix.sync.aligned.m8n8.x4.shared.b16 {%0,%1,%2,%3}, [%4];"
                 : "=r"(r0), "=r"(r1), "=r"(r2), "=r"(r3) : "r"(addr));
}
__device__ __forceinline__ void mma16816(float d[4], const unsigned a[4],
                                         unsigned b0, unsigned b1) {
    asm volatile("mma.sync.aligned.m16n8k16.row.col.f32.bf16.bf16.f32 "
                 "{%0,%1,%2,%3},{%4,%5,%6,%7},{%8,%9},{%0,%1,%2,%3};"
                 : "+f"(d[0]), "+f"(d[1]), "+f"(d[2]), "+f"(d[3])
                 : "r"(a[0]), "r"(a[1]), "r"(a[2]), "r"(a[3]),
                   "r"(b0), "r"(b1));
}

// ---------------- epilogue: 3 MUFU per output -------------------------------
// giou = inter/uni - (aC-uni)/aC = (inter*aC + uni*uni) * rcp(uni*aC) - 1
// cls * matchvec = rcp((sd+1)*(ds+1))
__device__ __forceinline__ float epi_one(float dot, float nsum,
                                         float ex0, float ey0, float ex1, float ey1,
                                         float area_e, float ecx, float ecy, float score,
                                         float bx0, float by0, float bx1, float by1,
                                         float area_b, float vx, float vy) {
    float iw = fmaxf(fminf(ex1, bx1) - fmaxf(ex0, bx0), 0.f);
    float ih = fmaxf(fminf(ey1, by1) - fmaxf(ey0, by0), 0.f);
    float inter = iw * ih;
    float uni = area_e + area_b - inter;
    float cw = fmaxf(ex1, bx1) - fminf(ex0, bx0);
    float ch = fmaxf(ey1, by1) - fminf(ey0, by0);
    float aC = cw * ch;
    float r1 = __fdividef(1.f, uni * aC);
    float g  = fmaxf(fmaf(fmaf(uni, uni, inter * aC), r1, -1.f), 0.f);
    float d2 = fmaxf(fmaf(-2.f, dot, nsum), 1e-12f);
    float sd = d2 * rsqrtf(d2);
    float ds = fabsf(vx - ecx) + fabsf(vy - ecy);
    float r2 = __fdividef(1.f, (sd + 1.f) * (ds + 1.f));
    return score * g * r2;
}

// ---------------- stage 2: dual bf16 tensor-core GEMM + epilogue ------------
extern __shared__ char dyn_smem[];

__global__ __launch_bounds__(256) void pair_kernel(float* __restrict__ out) {
    __shared__ __align__(16) float sEm[TS * 8];
    __shared__ __align__(16) float sRm[TS * 16];

    char* sAs = dyn_smem;                 // rs_prob tile  [64][168] bf16
    char* sAo = dyn_smem + TS * LDSB;     // ro_prob tile
    char* sB  = dyn_smem + 2 * TS * LDSB; // ent_prob tile

    int b  = blockIdx.z;
    int rb = blockIdx.y * TS;
    int eb = blockIdx.x * TS;
    int t  = threadIdx.x;

    // meta tiles
    {
        const float* em = g_ent_meta + (size_t)(b * NPAD + eb) * 8;
        const float* rm = g_rel_meta + (size_t)(b * NPAD + rb) * 16;
        for (int i = t; i < TS * 8;  i += 256) sEm[i] = em[i];
        for (int i = t; i < TS * 16; i += 256) sRm[i] = rm[i];
    }
    // prob tiles: full K resident, one shot (linear uint4 reads, padded smem rows)
    {
        const uint4* gA = (const uint4*)(g_rs_prob  + (size_t)(b * NPAD + rb) * KP);
        const uint4* gO = (const uint4*)(g_ro_prob  + (size_t)(b * NPAD + rb) * KP);
        const uint4* gB = (const uint4*)(g_ent_prob + (size_t)(b * NPAD + eb) * KP);
        for (int i = t; i < TS * 20; i += 256) {   // 20 uint4 per 160-half row
            int row = i / 20, c = i % 20;
            int off = row * LDSB + c * 16;
            *(uint4*)(sAs + off) = gA[i];
            *(uint4*)(sAo + off) = gO[i];
            *(uint4*)(sB  + off) = gB[i];
        }
    }
    __syncthreads();

    int lane = t & 31, warp = t >> 5;
    int mw = warp & 3, nw = warp >> 2;    // 4 warps along M, 2 along N
    int gid = lane >> 2, qid = lane & 3;

    // per-lane ldmatrix base addresses (k0 = 0)
    unsigned aAddrS, aAddrO, bAddr0, bAddr1;
    {
        unsigned base = (unsigned)__cvta_generic_to_shared(dyn_smem);
        int arow = 16 * mw + (lane & 15);
        int akb  = (lane >> 4) << 3;                 // k-block 0 / 8
        aAddrS = base + arow * LDSB + akb * 2;
        aAddrO = aAddrS + TS * LDSB;
        int brow = 32 * nw + ((lane >> 4) << 3) + (lane & 7);
        int bkb  = ((lane >> 3) & 1) << 3;
        bAddr0 = base + 2 * TS * LDSB + brow * LDSB + bkb * 2;   // n-tiles 0,1
        bAddr1 = bAddr0 + 16 * LDSB;                              // n-tiles 2,3
    }

    float accS[4][4] = {}, accO[4][4] = {};

#pragma unroll
    for (int ks = 0; ks < KP / 16; ks++) {
        unsigned koff = ks * 32;   // 16 halves * 2B
        unsigned as[4], ao[4], b01[4], b23[4];
        ldsm4(as[0],  as[1],  as[2],  as[3],  aAddrS + koff);
        ldsm4(ao[0],  ao[1],  ao[2],  ao[3],  aAddrO + koff);
        ldsm4(b01[0], b01[1], b01[2], b01[3], bAddr0 + koff);
        ldsm4(b23[0], b23[1], b23[2], b23[3], bAddr1 + koff);
        mma16816(accS[0], as, b01[0], b01[1]);
        mma16816(accS[1], as, b01[2], b01[3]);
        mma16816(accS[2], as, b23[0], b23[1]);
        mma16816(accS[3], as, b23[2], b23[3]);
        mma16816(accO[0], ao, b01[0], b01[1]);
        mma16816(accO[1], ao, b01[2], b01[3]);
        mma16816(accO[2], ao, b23[0], b23[1]);
        mma16816(accO[3], ao, b23[2], b23[3]);
    }

    // ---------------- epilogue ----------------
    const size_t outS = (size_t)b * NR * NE;
    const size_t outO = (size_t)BB * NR * NE + outS;

#pragma unroll
    for (int h = 0; h < 2; h++) {
        int rl = 16 * mw + gid + 8 * h;
        int r  = rb + rl;
        if (r >= NR) continue;
        const float* R = sRm + rl * 16;
        float rsx0 = R[0], rsy0 = R[1], rsx1 = R[2], rsy1 = R[3];
        float rox0 = R[4], roy0 = R[5], rox1 = R[6], roy1 = R[7];
        float v0 = R[8], v1 = R[9], v2 = R[10], v3 = R[11];
        float n_rs = R[12], n_ro = R[13];
        float area_rs = (rsx1 - rsx0) * (rsy1 - rsy0);
        float area_ro = (rox1 - rox0) * (roy1 - roy0);
#pragma unroll
        for (int j = 0; j < 4; j++) {
            int el = 32 * nw + 8 * j + qid * 2;
            int e  = eb + el;
            if (e >= NE) continue;   // e even -> (e, e+1) both < NE when taken
            const float* E0 = sEm + el * 8;
            const float* E1 = E0 + 8;
            float a_e0 = (E0[2] - E0[0]) * (E0[3] - E0[1]);
            float a_e1 = (E1[2] - E1[0]) * (E1[3] - E1[1]);

            float s0 = epi_one(accS[j][2 * h + 0], n_rs + E0[7],
                               E0[0], E0[1], E0[2], E0[3], a_e0, E0[4], E0[5], E0[6],
                               rsx0, rsy0, rsx1, rsy1, area_rs, v0, v1);
            float s1 = epi_one(accS[j][2 * h + 1], n_rs + E1[7],
                               E1[0], E1[1], E1[2], E1[3], a_e1, E1[4], E1[5], E1[6],
                               rsx0, rsy0, rsx1, rsy1, area_rs, v0, v1);
            float o0 = epi_one(accO[j][2 * h + 0], n_ro + E0[7],
                               E0[0], E0[1], E0[2], E0[3], a_e0, E0[4], E0[5], E0[6],
                               rox0, roy0, rox1, roy1, area_ro, v2, v3);
            float o1 = epi_one(accO[j][2 * h + 1], n_ro + E1[7],
                               E1[0], E1[1], E1[2], E1[3], a_e1, E1[4], E1[5], E1[6],
                               rox0, roy0, rox1, roy1, area_ro, v2, v3);

            *(float2*)&out[outS + (size_t)r * NE + e] = make_float2(s0, s1);
            *(float2*)&out[outO + (size_t)r * NE + e] = make_float2(o0, o1);
        }
    }
}

// ---------------- launch -----------------------------------------------------
extern "C" void kernel_launch(void* const* d_in, const int* in_sizes, int n_in,
                              void* d_out, int out_size) {
    const float* pred_boxes     = (const float*)d_in[0];
    const float* pred_logits    = (const float*)d_in[1];
    const float* rel_obj_logits = (const float*)d_in[2];
    const float* rel_sub_logits = (const float*)d_in[3];
    const float* rel_obj_box    = (const float*)d_in[4];
    const float* rel_sub_box    = (const float*)d_in[5];
    const float* rel_vec        = (const float*)d_in[6];
    const float* target_sizes   = (const float*)d_in[7];
    float* out = (float*)d_out;

    // stage 1: unified — 3 tasks * BB*NPAD rows, one warp per row
    int warps = 3 * BB * NPAD;            // 98304
    pre_all<<<warps / 8, 256>>>(pred_boxes, pred_logits,
                                rel_obj_logits, rel_sub_logits,
                                rel_obj_box, rel_sub_box, rel_vec, target_sizes);

    // stage 2: dual bf16 tensor-core GEMM + epilogue (full-K resident smem)
    const int dyn_bytes = 3 * TS * LDSB;  // 64512
    cudaFuncSetAttribute(pair_kernel,
                         cudaFuncAttributeMaxDynamicSharedMemorySize, dyn_bytes);
    dim3 grid(NPAD / TS, NPAD / TS, BB);  // (8, 8, 64)
    pair_kernel<<<grid, 256, dyn_bytes>>>(out);
}

// round 16
// speedup vs baseline: 1.0039x; 1.0039x over previous
#include <cuda_runtime.h>
#include <cuda_bf16.h>
#include <cstdint>

#define BB   64
#define NE   500
#define NR   500
#define NPAD 512
#define C1   151      // classes + 1
#define NC   150      // kept classes
#define KP   160      // padded K for dot products
#define TS   64       // tile size (rows/cols per block)
#define LDH  168      // smem row stride in bf16 halves
#define LDSB (LDH*2)  // smem row stride bytes = 336

// ---------------- scratch (device globals: no allocation allowed) ----------
__device__ __align__(16) __nv_bfloat16 g_ent_prob[(size_t)BB * NPAD * KP];
__device__ __align__(16) __nv_bfloat16 g_rs_prob [(size_t)BB * NPAD * KP];
__device__ __align__(16) __nv_bfloat16 g_ro_prob [(size_t)BB * NPAD * KP];
__device__ float g_ent_meta[(size_t)BB * NPAD * 8];   // x0,y0,x1,y1,cx,cy,score,norm2
__device__ float g_rel_meta[(size_t)BB * NPAD * 16];  // rs box(4), ro box(4), vec(4), n_rs, n_ro, pad2

// ---------------- fast softmax (one warp, one row) ---------------------------
// writes bf16 probs (first NC kept, KP-NC zero-padded); returns ||p||^2 in all
// lanes and max-prob-over-NC ("score") in all lanes.
__device__ __forceinline__ float softmax_row_fast(const float* __restrict__ lg,
                                                  __nv_bfloat16* __restrict__ prob,
                                                  int lane, float& score) {
    float v[5];
    float m = -1e30f, m150 = -1e30f;
#pragma unroll
    for (int k = 0; k < 5; k++) {
        int i = lane + k * 32;
        float x = (i < C1) ? lg[i] : -1e30f;
        v[k] = x;
        m = fmaxf(m, x);
        if (i < NC) m150 = fmaxf(m150, x);
    }
#pragma unroll
    for (int o = 16; o > 0; o >>= 1) {
        m    = fmaxf(m,    __shfl_xor_sync(0xffffffffu, m,    o));
        m150 = fmaxf(m150, __shfl_xor_sync(0xffffffffu, m150, o));
    }
    float s = 0.f;
#pragma unroll
    for (int k = 0; k < 5; k++) {
        int i = lane + k * 32;
        float ex = (i < C1) ? __expf(v[k] - m) : 0.f;
        v[k] = ex;
        s += ex;
    }
#pragma unroll
    for (int o = 16; o > 0; o >>= 1) s += __shfl_xor_sync(0xffffffffu, s, o);
    float inv = 1.f / s;
    float n2 = 0.f;
#pragma unroll
    for (int k = 0; k < 5; k++) {
        int i = lane + k * 32;
        if (i < KP) {
            float p = (i < NC) ? v[k] * inv : 0.f;
            prob[i] = __float2bfloat16(p);
            n2 += p * p;
        }
    }
#pragma unroll
    for (int o = 16; o > 0; o >>= 1) n2 += __shfl_xor_sync(0xffffffffu, n2, o);
    score = __expf(m150 - m) * inv;
    return n2;
}

// ---------------- stage 1: unified preprocessing (1 softmax per warp) -------
// task 0: entity rows  (b, e)   -> g_ent_prob + g_ent_meta
// task 1: rel-sub rows (b, r)   -> g_rs_prob  + rel_meta[0..3],[8..12],[14]
// task 2: rel-obj rows (b, r)   -> g_ro_prob  + rel_meta[4..7],[13],[15]
__global__ void pre_all(const float* __restrict__ boxes,
                        const float* __restrict__ logits,
                        const float* __restrict__ ro_logits,
                        const float* __restrict__ rs_logits,
                        const float* __restrict__ ro_box,
                        const float* __restrict__ rs_box,
                        const float* __restrict__ rel_vec,
                        const float* __restrict__ tsz) {
    int gw   = blockIdx.x * (blockDim.x >> 5) + (threadIdx.x >> 5);
    int lane = threadIdx.x & 31;
    int task = gw >> 15;              // / (BB*NPAD)
    int idx  = gw & (BB * NPAD - 1);
    int b    = idx >> 9;
    int row  = idx & (NPAD - 1);
    size_t rowi = (size_t)idx;

    if (task == 0) {
        __nv_bfloat16* prob = g_ent_prob + rowi * KP;
        float* meta = g_ent_meta + rowi * 8;
        if (row >= NE) {
            __nv_bfloat16 z = __float2bfloat16(0.f);
            for (int i = lane; i < KP; i += 32) prob[i] = z;
            if (lane < 8) meta[lane] = 0.f;
            return;
        }
        float score;
        float n2 = softmax_row_fast(logits + (size_t)(b * NE + row) * C1, prob, lane, score);
        if (lane == 0) {
            float H = tsz[b * 2 + 0], W = tsz[b * 2 + 1];
            const float* bx = boxes + ((size_t)(b * NE + row)) * 4;
            float cx = bx[0], cy = bx[1], w = bx[2], h = bx[3];
            meta[0] = (cx - 0.5f * w) * W;
            meta[1] = (cy - 0.5f * h) * H;
            meta[2] = (cx + 0.5f * w) * W;
            meta[3] = (cy + 0.5f * h) * H;
            meta[4] = cx * W;
            meta[5] = cy * H;
            meta[6] = score;
            meta[7] = n2;
        }
    } else if (task == 1) {
        __nv_bfloat16* prob = g_rs_prob + rowi * KP;
        float* meta = g_rel_meta + rowi * 16;
        if (row >= NR) {
            __nv_bfloat16 z = __float2bfloat16(0.f);
            for (int i = lane; i < KP; i += 32) prob[i] = z;
            if (lane == 0) {
                meta[0] = meta[1] = meta[2] = meta[3] = 0.f;
                meta[8] = meta[9] = meta[10] = meta[11] = 0.f;
                meta[12] = 0.f; meta[14] = 0.f;
            }
            return;
        }
        float score;
        float n2 = softmax_row_fast(rs_logits + (size_t)(b * NR + row) * C1, prob, lane, score);
        if (lane == 0) {
            float H = tsz[b * 2 + 0], W = tsz[b * 2 + 1];
            size_t bi = (size_t)(b * NR + row) * 4;
            const float* sb = rs_box + bi;
            const float* rv = rel_vec + bi;
            float cx = sb[0], cy = sb[1], w = sb[2], h = sb[3];
            meta[0] = (cx - 0.5f * w) * W; meta[1] = (cy - 0.5f * h) * H;
            meta[2] = (cx + 0.5f * w) * W; meta[3] = (cy + 0.5f * h) * H;
            meta[8]  = rv[0] * W; meta[9]  = rv[1] * H;
            meta[10] = rv[2] * W; meta[11] = rv[3] * H;
            meta[12] = n2;
            meta[14] = 0.f;
        }
    } else {
        __nv_bfloat16* prob = g_ro_prob + rowi * KP;
        float* meta = g_rel_meta + rowi * 16;
        if (row >= NR) {
            __nv_bfloat16 z = __float2bfloat16(0.f);
            for (int i = lane; i < KP; i += 32) prob[i] = z;
            if (lane == 0) {
                meta[4] = meta[5] = meta[6] = meta[7] = 0.f;
                meta[13] = 0.f; meta[15] = 0.f;
            }
            return;
        }
        float score;
        float n2 = softmax_row_fast(ro_logits + (size_t)(b * NR + row) * C1, prob, lane, score);
        if (lane == 0) {
            float H = tsz[b * 2 + 0], W = tsz[b * 2 + 1];
            size_t bi = (size_t)(b * NR + row) * 4;
            const float* ob = ro_box + bi;
            float cx = ob[0], cy = ob[1], w = ob[2], h = ob[3];
            meta[4] = (cx - 0.5f * w) * W; meta[5] = (cy - 0.5f * h) * H;
            meta[6] = (cx + 0.5f * w) * W; meta[7] = (cy + 0.5f * h) * H;
            meta[13] = n2;
            meta[15] = 0.f;
        }
    }
}

// ---------------- mma / ldmatrix helpers ------------------------------------
__device__ __forceinline__ void ldsm4(unsigned& r0, unsigned& r1, unsigned& r2,
                                      unsigned& r3, unsigned addr) {
    asm volatile("ldmatrix.sync.aligned.m8n8.x4.shared.b16 {%0,%1,%2,%3}, [%4];"
                 : "=r"(r0), "=r"(r1), "=r"(r2), "=r"(r3) : "r"(addr));
}
__device__ __forceinline__ void mma16816(float d[4], const unsigned a[4],
                                         unsigned b0, unsigned b1) {
    asm volatile("mma.sync.aligned.m16n8k16.row.col.f32.bf16.bf16.f32 "
                 "{%0,%1,%2,%3},{%4,%5,%6,%7},{%8,%9},{%0,%1,%2,%3};"
                 : "+f"(d[0]), "+f"(d[1]), "+f"(d[2]), "+f"(d[3])
                 : "r"(a[0]), "r"(a[1]), "r"(a[2]), "r"(a[3]),
                   "r"(b0), "r"(b1));
}

// ---------------- epilogue: 3 MUFU per output -------------------------------
// giou = inter/uni - (aC-uni)/aC = (inter*aC + uni*uni) * rcp(uni*aC) - 1
// cls * matchvec = rcp((sd+1)*(ds+1))
__device__ __forceinline__ float epi_one(float dot, float nsum,
                                         float ex0, float ey0, float ex1, float ey1,
                                         float area_e, float ecx, float ecy, float score,
                                         float bx0, float by0, float bx1, float by1,
                                         float area_b, float vx, float vy) {
    float iw = fmaxf(fminf(ex1, bx1) - fmaxf(ex0, bx0), 0.f);
    float ih = fmaxf(fminf(ey1, by1) - fmaxf(ey0, by0), 0.f);
    float inter = iw * ih;
    float uni = area_e + area_b - inter;
    float cw = fmaxf(ex1, bx1) - fminf(ex0, bx0);
    float ch = fmaxf(ey1, by1) - fminf(ey0, by0);
    float aC = cw * ch;
    float r1 = __fdividef(1.f, uni * aC);
    float g  = fmaxf(fmaf(fmaf(uni, uni, inter * aC), r1, -1.f), 0.f);
    float d2 = fmaxf(fmaf(-2.f, dot, nsum), 1e-12f);
    float sd = d2 * rsqrtf(d2);
    float ds = fabsf(vx - ecx) + fabsf(vy - ecy);
    float r2 = __fdividef(1.f, (sd + 1.f) * (ds + 1.f));
    return score * g * r2;
}

// ---------------- stage 2: dual bf16 tensor-core GEMM + epilogue ------------
extern __shared__ char dyn_smem[];

__global__ __launch_bounds__(256) void pair_kernel(float* __restrict__ out) {
    __shared__ __align__(16) float sEm[TS * 8];
    __shared__ __align__(16) float sRm[TS * 16];

    char* sAs = dyn_smem;                 // rs_prob tile  [64][168] bf16
    char* sAo = dyn_smem + TS * LDSB;     // ro_prob tile
    char* sB  = dyn_smem + 2 * TS * LDSB; // ent_prob tile

    int b  = blockIdx.z;
    int rb = blockIdx.y * TS;
    int eb = blockIdx.x * TS;
    int t  = threadIdx.x;

    // meta tiles
    {
        const float* em = g_ent_meta + (size_t)(b * NPAD + eb) * 8;
        const float* rm = g_rel_meta + (size_t)(b * NPAD + rb) * 16;
        for (int i = t; i < TS * 8;  i += 256) sEm[i] = em[i];
        for (int i = t; i < TS * 16; i += 256) sRm[i] = rm[i];
    }
    // prob tiles: full K resident, one shot (linear uint4 reads, padded smem rows)
    {
        const uint4* gA = (const uint4*)(g_rs_prob  + (size_t)(b * NPAD + rb) * KP);
        const uint4* gO = (const uint4*)(g_ro_prob  + (size_t)(b * NPAD + rb) * KP);
        const uint4* gB = (const uint4*)(g_ent_prob + (size_t)(b * NPAD + eb) * KP);
        for (int i = t; i < TS * 20; i += 256) {   // 20 uint4 per 160-half row
            int row = i / 20, c = i % 20;
            int off = row * LDSB + c * 16;
            *(uint4*)(sAs + off) = gA[i];
            *(uint4*)(sAo + off) = gO[i];
            *(uint4*)(sB  + off) = gB[i];
        }
    }
    __syncthreads();

    int lane = t & 31, warp = t >> 5;
    int mw = warp & 3, nw = warp >> 2;    // 4 warps along M, 2 along N
    int gid = lane >> 2, qid = lane & 3;

    // per-lane ldmatrix base addresses (k0 = 0)
    unsigned aAddrS, aAddrO, bAddr0, bAddr1;
    {
        unsigned base = (unsigned)__cvta_generic_to_shared(dyn_smem);
        int arow = 16 * mw + (lane & 15);
        int akb  = (lane >> 4) << 3;                 // k-block 0 / 8
        aAddrS = base + arow * LDSB + akb * 2;
        aAddrO = aAddrS + TS * LDSB;
        int brow = 32 * nw + ((lane >> 4) << 3) + (lane & 7);
        int bkb  = ((lane >> 3) & 1) << 3;
        bAddr0 = base + 2 * TS * LDSB + brow * LDSB + bkb * 2;   // n-tiles 0,1
        bAddr1 = bAddr0 + 16 * LDSB;                              // n-tiles 2,3
    }

    float accS[4][4] = {}, accO[4][4] = {};

#pragma unroll
    for (int ks = 0; ks < KP / 16; ks++) {
        unsigned koff = ks * 32;   // 16 halves * 2B
        unsigned as[4], ao[4], b01[4], b23[4];
        ldsm4(as[0],  as[1],  as[2],  as[3],  aAddrS + koff);
        ldsm4(ao[0],  ao[1],  ao[2],  ao[3],  aAddrO + koff);
        ldsm4(b01[0], b01[1], b01[2], b01[3], bAddr0 + koff);
        ldsm4(b23[0], b23[1], b23[2], b23[3], bAddr1 + koff);
        mma16816(accS[0], as, b01[0], b01[1]);
        mma16816(accS[1], as, b01[2], b01[3]);
        mma16816(accS[2], as, b23[0], b23[1]);
        mma16816(accS[3], as, b23[2], b23[3]);
        mma16816(accO[0], ao, b01[0], b01[1]);
        mma16816(accO[1], ao, b01[2], b01[3]);
        mma16816(accO[2], ao, b23[0], b23[1]);
        mma16816(accO[3], ao, b23[2], b23[3]);
    }

    // ---------------- epilogue ----------------
    const size_t outS = (size_t)b * NR * NE;
    const size_t outO = (size_t)BB * NR * NE + outS;

#pragma unroll
    for (int h = 0; h < 2; h++) {
        int rl = 16 * mw + gid + 8 * h;
        int r  = rb + rl;
        if (r >= NR) continue;
        const float* R = sRm + rl * 16;
        float rsx0 = R[0], rsy0 = R[1], rsx1 = R[2], rsy1 = R[3];
        float rox0 = R[4], roy0 = R[5], rox1 = R[6], roy1 = R[7];
        float v0 = R[8], v1 = R[9], v2 = R[10], v3 = R[11];
        float n_rs = R[12], n_ro = R[13];
        float area_rs = (rsx1 - rsx0) * (rsy1 - rsy0);
        float area_ro = (rox1 - rox0) * (roy1 - roy0);
#pragma unroll
        for (int j = 0; j < 4; j++) {
            int el = 32 * nw + 8 * j + qid * 2;
            int e  = eb + el;
            if (e >= NE) continue;   // e even -> (e, e+1) both < NE when taken
            const float* E0 = sEm + el * 8;
            const float* E1 = E0 + 8;
            float a_e0 = (E0[2] - E0[0]) * (E0[3] - E0[1]);
            float a_e1 = (E1[2] - E1[0]) * (E1[3] - E1[1]);

            float s0 = epi_one(accS[j][2 * h + 0], n_rs + E0[7],
                               E0[0], E0[1], E0[2], E0[3], a_e0, E0[4], E0[5], E0[6],
                               rsx0, rsy0, rsx1, rsy1, area_rs, v0, v1);
            float s1 = epi_one(accS[j][2 * h + 1], n_rs + E1[7],
                               E1[0], E1[1], E1[2], E1[3], a_e1, E1[4], E1[5], E1[6],
                               rsx0, rsy0, rsx1, rsy1, area_rs, v0, v1);
            float o0 = epi_one(accO[j][2 * h + 0], n_ro + E0[7],
                               E0[0], E0[1], E0[2], E0[3], a_e0, E0[4], E0[5], E0[6],
                               rox0, roy0, rox1, roy1, area_ro, v2, v3);
            float o1 = epi_one(accO[j][2 * h + 1], n_ro + E1[7],
                               E1[0], E1[1], E1[2], E1[3], a_e1, E1[4], E1[5], E1[6],
                               rox0, roy0, rox1, roy1, area_ro, v2, v3);

            *(float2*)&out[outS + (size_t)r * NE + e] = make_float2(s0, s1);
            *(float2*)&out[outO + (size_t)r * NE + e] = make_float2(o0, o1);
        }
    }
}

// ---------------- launch -----------------------------------------------------
extern "C" void kernel_launch(void* const* d_in, const int* in_sizes, int n_in,
                              void* d_out, int out_size) {
    const float* pred_boxes     = (const float*)d_in[0];
    const float* pred_logits    = (const float*)d_in[1];
    const float* rel_obj_logits = (const float*)d_in[2];
    const float* rel_sub_logits = (const float*)d_in[3];
    const float* rel_obj_box    = (const float*)d_in[4];
    const float* rel_sub_box    = (const float*)d_in[5];
    const float* rel_vec        = (const float*)d_in[6];
    const float* target_sizes   = (const float*)d_in[7];
    float* out = (float*)d_out;

    // stage 1: unified — 3 tasks * BB*NPAD rows, one warp per row
    int warps = 3 * BB * NPAD;            // 98304
    pre_all<<<warps / 8, 256>>>(pred_boxes, pred_logits,
                                rel_obj_logits, rel_sub_logits,
                                rel_obj_box, rel_sub_box, rel_vec, target_sizes);

    // stage 2: dual bf16 tensor-core GEMM + epilogue (full-K resident smem)
    const int dyn_bytes = 3 * TS * LDSB;  // 64512
    cudaFuncSetAttribute(pair_kernel,
                         cudaFuncAttributeMaxDynamicSharedMemorySize, dyn_bytes);
    dim3 grid(NPAD / TS, NPAD / TS, BB);  // (8, 8, 64)
    pair_kernel<<<grid, 256, dyn_bytes>>>(out);
}

// round 17
// speedup vs baseline: 1.0163x; 1.0123x over previous
#include <cuda_runtime.h>
#include <cuda_bf16.h>
#include <cstdint>

#define BB   64
#define NE   500
#define NR   500
#define NPAD 512
#define C1   151      // classes + 1
#define NC   150      // kept classes
#define KP   160      // padded K for dot products
#define TS   64       // tile size (rows/cols per block)
#define LDH  168      // smem row stride in bf16 halves
#define LDSB (LDH*2)  // smem row stride bytes = 336

// ---------------- scratch (device globals: no allocation allowed) ----------
__device__ __align__(16) __nv_bfloat16 g_ent_prob[(size_t)BB * NPAD * KP];
__device__ __align__(16) __nv_bfloat16 g_rs_prob [(size_t)BB * NPAD * KP];
__device__ __align__(16) __nv_bfloat16 g_ro_prob [(size_t)BB * NPAD * KP];
__device__ float g_ent_meta[(size_t)BB * NPAD * 8];   // x0,y0,x1,y1,cx,cy,score,norm2
__device__ float g_rel_meta[(size_t)BB * NPAD * 16];  // rs box(4), ro box(4), vec(4), n_rs, n_ro, pad2

// ---------------- fast softmax (one warp, one row; pair-packed stores) ------
// lane owns columns (2*lane + 64k, 2*lane + 64k + 1), k = 0..2 (covers 0..191,
// writes only < KP). Writes bf16x2 probs (first NC kept, KP-NC zero-padded);
// returns ||p||^2 in all lanes and max-prob-over-NC ("score") in all lanes.
__device__ __forceinline__ float softmax_row_fast(const float* __restrict__ lg,
                                                  __nv_bfloat16* __restrict__ prob,
                                                  int lane, float& score) {
    float x0[3], x1[3];
    float m = -1e30f, m150 = -1e30f;
#pragma unroll
    for (int k = 0; k < 3; k++) {
        int i0 = 2 * lane + 64 * k;
        float a = (i0     < C1) ? lg[i0]     : -1e30f;
        float c = (i0 + 1 < C1) ? lg[i0 + 1] : -1e30f;
        x0[k] = a; x1[k] = c;
        m = fmaxf(m, fmaxf(a, c));
        float a1 = (i0     < NC) ? a : -1e30f;
        float c1 = (i0 + 1 < NC) ? c : -1e30f;
        m150 = fmaxf(m150, fmaxf(a1, c1));
    }
#pragma unroll
    for (int o = 16; o > 0; o >>= 1) {
        m    = fmaxf(m,    __shfl_xor_sync(0xffffffffu, m,    o));
        m150 = fmaxf(m150, __shfl_xor_sync(0xffffffffu, m150, o));
    }
    float s = 0.f;
#pragma unroll
    for (int k = 0; k < 3; k++) {
        int i0 = 2 * lane + 64 * k;
        float e0 = (i0     < C1) ? __expf(x0[k] - m) : 0.f;
        float e1 = (i0 + 1 < C1) ? __expf(x1[k] - m) : 0.f;
        x0[k] = e0; x1[k] = e1;
        s += e0 + e1;
    }
#pragma unroll
    for (int o = 16; o > 0; o >>= 1) s += __shfl_xor_sync(0xffffffffu, s, o);
    float inv = 1.f / s;
    float n2 = 0.f;
#pragma unroll
    for (int k = 0; k < 3; k++) {
        int i0 = 2 * lane + 64 * k;
        if (i0 < KP) {
            float p0 = (i0     < NC) ? x0[k] * inv : 0.f;
            float p1 = (i0 + 1 < NC) ? x1[k] * inv : 0.f;
            ((__nv_bfloat162*)prob)[lane + 32 * k] = __floats2bfloat162_rn(p0, p1);
            n2 += p0 * p0 + p1 * p1;
        }
    }
#pragma unroll
    for (int o = 16; o > 0; o >>= 1) n2 += __shfl_xor_sync(0xffffffffu, n2, o);
    score = __expf(m150 - m) * inv;
    return n2;
}

__device__ __forceinline__ void zero_prob_row(__nv_bfloat16* __restrict__ prob, int lane) {
    __nv_bfloat162 z = __floats2bfloat162_rn(0.f, 0.f);
    for (int i = lane; i < KP / 2; i += 32) ((__nv_bfloat162*)prob)[i] = z;
}

// ---------------- stage 1: unified preprocessing (1 softmax per warp) -------
__global__ void pre_all(const float* __restrict__ boxes,
                        const float* __restrict__ logits,
                        const float* __restrict__ ro_logits,
                        const float* __restrict__ rs_logits,
                        const float* __restrict__ ro_box,
                        const float* __restrict__ rs_box,
                        const float* __restrict__ rel_vec,
                        const float* __restrict__ tsz) {
    int gw   = blockIdx.x * (blockDim.x >> 5) + (threadIdx.x >> 5);
    int lane = threadIdx.x & 31;
    int task = gw >> 15;              // / (BB*NPAD)
    int idx  = gw & (BB * NPAD - 1);
    int b    = idx >> 9;
    int row  = idx & (NPAD - 1);
    size_t rowi = (size_t)idx;

    if (task == 0) {
        __nv_bfloat16* prob = g_ent_prob + rowi * KP;
        float* meta = g_ent_meta + rowi * 8;
        if (row >= NE) {
            zero_prob_row(prob, lane);
            if (lane < 8) meta[lane] = 0.f;
            return;
        }
        float score;
        float n2 = softmax_row_fast(logits + (size_t)(b * NE + row) * C1, prob, lane, score);
        if (lane == 0) {
            float H = tsz[b * 2 + 0], W = tsz[b * 2 + 1];
            const float* bx = boxes + ((size_t)(b * NE + row)) * 4;
            float cx = bx[0], cy = bx[1], w = bx[2], h = bx[3];
            meta[0] = (cx - 0.5f * w) * W;
            meta[1] = (cy - 0.5f * h) * H;
            meta[2] = (cx + 0.5f * w) * W;
            meta[3] = (cy + 0.5f * h) * H;
            meta[4] = cx * W;
            meta[5] = cy * H;
            meta[6] = score;
            meta[7] = n2;
        }
    } else if (task == 1) {
        __nv_bfloat16* prob = g_rs_prob + rowi * KP;
        float* meta = g_rel_meta + rowi * 16;
        if (row >= NR) {
            zero_prob_row(prob, lane);
            if (lane == 0) {
                meta[0] = meta[1] = meta[2] = meta[3] = 0.f;
                meta[8] = meta[9] = meta[10] = meta[11] = 0.f;
                meta[12] = 0.f; meta[14] = 0.f;
            }
            return;
        }
        float score;
        float n2 = softmax_row_fast(rs_logits + (size_t)(b * NR + row) * C1, prob, lane, score);
        if (lane == 0) {
            float H = tsz[b * 2 + 0], W = tsz[b * 2 + 1];
            size_t bi = (size_t)(b * NR + row) * 4;
            const float* sb = rs_box + bi;
            const float* rv = rel_vec + bi;
            float cx = sb[0], cy = sb[1], w = sb[2], h = sb[3];
            meta[0] = (cx - 0.5f * w) * W; meta[1] = (cy - 0.5f * h) * H;
            meta[2] = (cx + 0.5f * w) * W; meta[3] = (cy + 0.5f * h) * H;
            meta[8]  = rv[0] * W; meta[9]  = rv[1] * H;
            meta[10] = rv[2] * W; meta[11] = rv[3] * H;
            meta[12] = n2;
            meta[14] = 0.f;
        }
    } else {
        __nv_bfloat16* prob = g_ro_prob + rowi * KP;
        float* meta = g_rel_meta + rowi * 16;
        if (row >= NR) {
            zero_prob_row(prob, lane);
            if (lane == 0) {
                meta[4] = meta[5] = meta[6] = meta[7] = 0.f;
                meta[13] = 0.f; meta[15] = 0.f;
            }
            return;
        }
        float score;
        float n2 = softmax_row_fast(ro_logits + (size_t)(b * NR + row) * C1, prob, lane, score);
        if (lane == 0) {
            float H = tsz[b * 2 + 0], W = tsz[b * 2 + 1];
            size_t bi = (size_t)(b * NR + row) * 4;
            const float* ob = ro_box + bi;
            float cx = ob[0], cy = ob[1], w = ob[2], h = ob[3];
            meta[4] = (cx - 0.5f * w) * W; meta[5] = (cy - 0.5f * h) * H;
            meta[6] = (cx + 0.5f * w) * W; meta[7] = (cy + 0.5f * h) * H;
            meta[13] = n2;
            meta[15] = 0.f;
        }
    }
}

// ---------------- mma / ldmatrix helpers ------------------------------------
__device__ __forceinline__ void ldsm4(unsigned& r0, unsigned& r1, unsigned& r2,
                                      unsigned& r3, unsigned addr) {
    asm volatile("ldmatrix.sync.aligned.m8n8.x4.shared.b16 {%0,%1,%2,%3}, [%4];"
                 : "=r"(r0), "=r"(r1), "=r"(r2), "=r"(r3) : "r"(addr));
}
__device__ __forceinline__ void mma16816(float d[4], const unsigned a[4],
                                         unsigned b0, unsigned b1) {
    asm volatile("mma.sync.aligned.m16n8k16.row.col.f32.bf16.bf16.f32 "
                 "{%0,%1,%2,%3},{%4,%5,%6,%7},{%8,%9},{%0,%1,%2,%3};"
                 : "+f"(d[0]), "+f"(d[1]), "+f"(d[2]), "+f"(d[3])
                 : "r"(a[0]), "r"(a[1]), "r"(a[2]), "r"(a[3]),
                   "r"(b0), "r"(b1));
}

// ---------------- epilogue: 2 MUFU, 8 FMNMX per output ----------------------
// giou_clipped / ((sd+1)(ds+1)) * score
//   = max(inter*aC + uni^2 - uni*aC, 0) * score / (uni*aC*(sd+1)*(ds+1))
// hull width: max(x1a,x1b)-min(x0a,x0b) = (w_a + w_b) - iwr  (iwr = raw inter w)
__device__ __forceinline__ float epi_one(float dot, float nsum,
                                         float ex0, float ey0, float ex1, float ey1,
                                         float wex, float wey, float area_e,
                                         float ecx, float ecy, float score,
                                         float bx0, float by0, float bx1, float by1,
                                         float wbx, float wby, float area_b,
                                         float vx, float vy) {
    float mnx = fminf(ex1, bx1), mxx = fmaxf(ex0, bx0);
    float mny = fminf(ey1, by1), mxy = fmaxf(ey0, by0);
    float iwr = mnx - mxx, ihr = mny - mxy;
    float iw = fmaxf(iwr, 0.f), ih = fmaxf(ihr, 0.f);
    float inter = iw * ih;
    float uni = (area_e + area_b) - inter;
    float cw = (wex + wbx) - iwr;
    float ch = (wey + wby) - ihr;
    float aC = cw * ch;
    float num = fmaxf(fmaf(uni, uni - aC, inter * aC), 0.f);
    float d2  = fmaxf(fmaf(-2.f, dot, nsum), 1e-12f);
    float sd1 = fmaf(d2, rsqrtf(d2), 1.f);
    float ds1 = fabsf(vx - ecx) + fabsf(vy - ecy) + 1.f;
    float den = (uni * aC) * (sd1 * ds1);
    return num * __fdividef(score, den);
}

// ---------------- stage 2: dual bf16 tensor-core GEMM + epilogue ------------
extern __shared__ char dyn_smem[];

__global__ __launch_bounds__(256) void pair_kernel(float* __restrict__ out) {
    __shared__ __align__(16) float sEm[TS * 8];
    __shared__ __align__(16) float sRm[TS * 16];

    char* sAs = dyn_smem;                 // rs_prob tile  [64][168] bf16
    char* sAo = dyn_smem + TS * LDSB;     // ro_prob tile
    char* sB  = dyn_smem + 2 * TS * LDSB; // ent_prob tile

    int b  = blockIdx.z;
    int rb = blockIdx.y * TS;
    int eb = blockIdx.x * TS;
    int t  = threadIdx.x;

    // meta tiles
    {
        const float* em = g_ent_meta + (size_t)(b * NPAD + eb) * 8;
        const float* rm = g_rel_meta + (size_t)(b * NPAD + rb) * 16;
        for (int i = t; i < TS * 8;  i += 256) sEm[i] = em[i];
        for (int i = t; i < TS * 16; i += 256) sRm[i] = rm[i];
    }
    // prob tiles: full K resident, one shot (linear uint4 reads, padded smem rows)
    {
        const uint4* gA = (const uint4*)(g_rs_prob  + (size_t)(b * NPAD + rb) * KP);
        const uint4* gO = (const uint4*)(g_ro_prob  + (size_t)(b * NPAD + rb) * KP);
        const uint4* gB = (const uint4*)(g_ent_prob + (size_t)(b * NPAD + eb) * KP);
        for (int i = t; i < TS * 20; i += 256) {   // 20 uint4 per 160-half row
            int row = i / 20, c = i % 20;
            int off = row * LDSB + c * 16;
            *(uint4*)(sAs + off) = gA[i];
            *(uint4*)(sAo + off) = gO[i];
            *(uint4*)(sB  + off) = gB[i];
        }
    }
    __syncthreads();

    int lane = t & 31, warp = t >> 5;
    int mw = warp & 3, nw = warp >> 2;    // 4 warps along M, 2 along N
    int gid = lane >> 2, qid = lane & 3;

    // per-lane ldmatrix base addresses (k0 = 0)
    unsigned aAddrS, aAddrO, bAddr0, bAddr1;
    {
        unsigned base = (unsigned)__cvta_generic_to_shared(dyn_smem);
        int arow = 16 * mw + (lane & 15);
        int akb  = (lane >> 4) << 3;                 // k-block 0 / 8
        aAddrS = base + arow * LDSB + akb * 2;
        aAddrO = aAddrS + TS * LDSB;
        int brow = 32 * nw + ((lane >> 4) << 3) + (lane & 7);
        int bkb  = ((lane >> 3) & 1) << 3;
        bAddr0 = base + 2 * TS * LDSB + brow * LDSB + bkb * 2;   // n-tiles 0,1
        bAddr1 = bAddr0 + 16 * LDSB;                              // n-tiles 2,3
    }

    float accS[4][4] = {}, accO[4][4] = {};

#pragma unroll
    for (int ks = 0; ks < KP / 16; ks++) {
        unsigned koff = ks * 32;   // 16 halves * 2B
        unsigned as[4], ao[4], b01[4], b23[4];
        ldsm4(as[0],  as[1],  as[2],  as[3],  aAddrS + koff);
        ldsm4(ao[0],  ao[1],  ao[2],  ao[3],  aAddrO + koff);
        ldsm4(b01[0], b01[1], b01[2], b01[3], bAddr0 + koff);
        ldsm4(b23[0], b23[1], b23[2], b23[3], bAddr1 + koff);
        mma16816(accS[0], as, b01[0], b01[1]);
        mma16816(accS[1], as, b01[2], b01[3]);
        mma16816(accS[2], as, b23[0], b23[1]);
        mma16816(accS[3], as, b23[2], b23[3]);
        mma16816(accO[0], ao, b01[0], b01[1]);
        mma16816(accO[1], ao, b01[2], b01[3]);
        mma16816(accO[2], ao, b23[0], b23[1]);
        mma16816(accO[3], ao, b23[2], b23[3]);
    }

    // ---------------- epilogue ----------------
    const size_t outS = (size_t)b * NR * NE;
    const size_t outO = (size_t)BB * NR * NE + outS;

#pragma unroll
    for (int h = 0; h < 2; h++) {
        int rl = 16 * mw + gid + 8 * h;
        int r  = rb + rl;
        if (r >= NR) continue;
        const float4* R4 = (const float4*)(sRm + rl * 16);
        float4 Rs = R4[0];   // rs box
        float4 Ro = R4[1];   // ro box
        float4 Rv = R4[2];   // rel vec
        float4 Rn = R4[3];   // n_rs, n_ro
        float w_rs_x = Rs.z - Rs.x, w_rs_y = Rs.w - Rs.y;
        float w_ro_x = Ro.z - Ro.x, w_ro_y = Ro.w - Ro.y;
        float area_rs = w_rs_x * w_rs_y;
        float area_ro = w_ro_x * w_ro_y;
#pragma unroll
        for (int j = 0; j < 4; j++) {
            int el = 32 * nw + 8 * j + qid * 2;
            int e  = eb + el;
            if (e >= NE) continue;   // e even -> (e, e+1) both < NE when taken
            const float4* E4 = (const float4*)(sEm + el * 8);
            float4 Ea0 = E4[0], Eb0 = E4[1];   // ent0: box | cx,cy,score,n2
            float4 Ea1 = E4[2], Eb1 = E4[3];   // ent1
            float we0x = Ea0.z - Ea0.x, we0y = Ea0.w - Ea0.y;
            float we1x = Ea1.z - Ea1.x, we1y = Ea1.w - Ea1.y;
            float a_e0 = we0x * we0y, a_e1 = we1x * we1y;

            float s0 = epi_one(accS[j][2 * h + 0], Rn.x + Eb0.w,
                               Ea0.x, Ea0.y, Ea0.z, Ea0.w, we0x, we0y, a_e0,
                               Eb0.x, Eb0.y, Eb0.z,
                               Rs.x, Rs.y, Rs.z, Rs.w, w_rs_x, w_rs_y, area_rs,
                               Rv.x, Rv.y);
            float s1 = epi_one(accS[j][2 * h + 1], Rn.x + Eb1.w,
                               Ea1.x, Ea1.y, Ea1.z, Ea1.w, we1x, we1y, a_e1,
                               Eb1.x, Eb1.y, Eb1.z,
                               Rs.x, Rs.y, Rs.z, Rs.w, w_rs_x, w_rs_y, area_rs,
                               Rv.x, Rv.y);
            float o0 = epi_one(accO[j][2 * h + 0], Rn.y + Eb0.w,
                               Ea0.x, Ea0.y, Ea0.z, Ea0.w, we0x, we0y, a_e0,
                               Eb0.x, Eb0.y, Eb0.z,
                               Ro.x, Ro.y, Ro.z, Ro.w, w_ro_x, w_ro_y, area_ro,
                               Rv.z, Rv.w);
            float o1 = epi_one(accO[j][2 * h + 1], Rn.y + Eb1.w,
                               Ea1.x, Ea1.y, Ea1.z, Ea1.w, we1x, we1y, a_e1,
                               Eb1.x, Eb1.y, Eb1.z,
                               Ro.x, Ro.y, Ro.z, Ro.w, w_ro_x, w_ro_y, area_ro,
                               Rv.z, Rv.w);

            *(float2*)&out[outS + (size_t)r * NE + e] = make_float2(s0, s1);
            *(float2*)&out[outO + (size_t)r * NE + e] = make_float2(o0, o1);
        }
    }
}

// ---------------- launch -----------------------------------------------------
extern "C" void kernel_launch(void* const* d_in, const int* in_sizes, int n_in,
                              void* d_out, int out_size) {
    const float* pred_boxes     = (const float*)d_in[0];
    const float* pred_logits    = (const float*)d_in[1];
    const float* rel_obj_logits = (const float*)d_in[2];
    const float* rel_sub_logits = (const float*)d_in[3];
    const float* rel_obj_box    = (const float*)d_in[4];
    const float* rel_sub_box    = (const float*)d_in[5];
    const float* rel_vec        = (const float*)d_in[6];
    const float* target_sizes   = (const float*)d_in[7];
    float* out = (float*)d_out;

    // stage 1: unified — 3 tasks * BB*NPAD rows, one warp per row
    int warps = 3 * BB * NPAD;            // 98304
    pre_all<<<warps / 8, 256>>>(pred_boxes, pred_logits,
                                rel_obj_logits, rel_sub_logits,
                                rel_obj_box, rel_sub_box, rel_vec, target_sizes);

    // stage 2: dual bf16 tensor-core GEMM + epilogue (full-K resident smem)
    const int dyn_bytes = 3 * TS * LDSB;  // 64512
    cudaFuncSetAttribute(pair_kernel,
                         cudaFuncAttributeMaxDynamicSharedMemorySize, dyn_bytes);
    dim3 grid(NPAD / TS, NPAD / TS, BB);  // (8, 8, 64)
    pair_kernel<<<grid, 256, dyn_bytes>>>(out);
}